// round 2
// baseline (speedup 1.0000x reference)
#include <cuda_runtime.h>
#include <cstdint>

typedef unsigned long long u64;

#define NB 16
#define NF 20
#define NT 128
#define ND 300
#define NH 256
#define NG 1024   // 4*H
#define NSEQ 8
#define SEQS 320  // NB*NF
#define NM 40960  // SEQS*NT

// Scratch: projection output (both dirs) 335 MB, repacked U 2 MB, mask 40 KB.
__device__ float g_xz[2ull * NM * NG];
__device__ float4 g_Upk[2 * NH * NH];     // [d][k][j] -> {Ui,Uf,Ug,Uo}
__device__ unsigned char g_mask[SEQS * NT];

__device__ __forceinline__ u64 pack2(float a, float b){
    u64 r; asm("mov.b64 %0, {%1, %2};" : "=l"(r) : "f"(a), "f"(b)); return r;
}
__device__ __forceinline__ void unpack2(u64 v, float& a, float& b){
    asm("mov.b64 {%0, %1}, %2;" : "=f"(a), "=f"(b) : "l"(v));
}
__device__ __forceinline__ u64 ffma2(u64 a, u64 b, u64 c){
    u64 d; asm("fma.rn.f32x2 %0, %1, %2, %3;" : "=l"(d) : "l"(a), "l"(b), "l"(c)); return d;
}

// ---------------------------------------------------------------------------
// Repack U into per-hidden-index gate quads: Upk[d][k][j] = {U[k][j], U[k][j+H],
// U[k][j+2H], U[k][j+3H]}. One float4 per (d,k,j).
// ---------------------------------------------------------------------------
__global__ void repack_u_kernel(const float* __restrict__ Uf, const float* __restrict__ Ub)
{
    int idx = blockIdx.x * 256 + threadIdx.x;      // 0 .. 2*256*256-1
    int d = idx >> 16;
    int k = (idx >> 8) & 255;
    int j = idx & 255;
    const float* U = d ? Ub : Uf;
    const float* r = U + (size_t)k * NG + j;
    float4 v = make_float4(r[0], r[NH], r[2 * NH], r[3 * NH]);
    g_Upk[idx] = v;
}

// ---------------------------------------------------------------------------
// Canonicalize the mask to u8 regardless of how the harness encoded bool.
// mask[0][0] and mask[0][1] are guaranteed true (lengths >= T/2 = 64), so:
//   byte0 == 0            -> float32 (1.0f = 00 00 80 3F)
//   byte1 != 0            -> uint8   (two adjacent true bytes)
//   else                  -> int32   (01 00 00 00 pattern)
// ---------------------------------------------------------------------------
__global__ void repack_mask_kernel(const unsigned char* __restrict__ raw)
{
    int idx = blockIdx.x * 256 + threadIdx.x;      // 0 .. SEQS*NT-1
    unsigned char b0 = raw[0], b1 = raw[1];
    unsigned char v;
    if (b0 == 0)      v = (((const float*)raw)[idx] != 0.0f);
    else if (b1 != 0) v = (raw[idx] != 0);
    else              v = (((const int*)raw)[idx] != 0);
    g_mask[idx] = v;
}

// ---------------------------------------------------------------------------
// Phase 1: xz[d][m][n] = x[m][:] @ W_d[:][n] + b_d[n]
// M=40960, K=300, N=1024 per direction. fp32 SGEMM with f32x2 FMAs.
// BM=64, BN=128, BK=20 (300 = 15*20), 256 threads, thread tile 4x8.
// ---------------------------------------------------------------------------
#define BM 64
#define BN 128
#define BK 20
#define KT 300

__global__ __launch_bounds__(256, 2) void proj_kernel(
    const float* __restrict__ x,
    const float* __restrict__ Wf, const float* __restrict__ bf,
    const float* __restrict__ Wb, const float* __restrict__ bb)
{
    __shared__ u64  Asd[BK][BM + 2];   // A values pre-duplicated as (a,a) pairs
    __shared__ float Bs[BK][BN];

    const int tid = threadIdx.x;
    const int m0  = blockIdx.x * BM;
    const int d   = blockIdx.y >> 3;
    const int n0  = (blockIdx.y & 7) * BN;
    const float* __restrict__ W    = d ? Wb : Wf;
    const float* __restrict__ bias = d ? bb : bf;
    const int tc = tid & 15;   // column group (x8)
    const int tr = tid >> 4;   // row group (x4)

    u64 acc[4][4];
    {
        const float* bp = bias + n0 + tc * 8;
        u64 b0 = pack2(bp[0], bp[1]);
        u64 b1 = pack2(bp[2], bp[3]);
        u64 b2 = pack2(bp[4], bp[5]);
        u64 b3 = pack2(bp[6], bp[7]);
        #pragma unroll
        for (int i = 0; i < 4; i++){ acc[i][0]=b0; acc[i][1]=b1; acc[i][2]=b2; acc[i][3]=b3; }
    }

    for (int kt = 0; kt < KT; kt += BK){
        #pragma unroll
        for (int i = 0; i < 5; i++){
            int li = tid + i * 256;
            int m  = li / BK;
            int k  = li % BK;
            float v = x[(size_t)(m0 + m) * ND + kt + k];
            Asd[k][m] = pack2(v, v);
        }
        #pragma unroll
        for (int i = 0; i < 10; i++){
            int li = tid + i * 256;
            int k  = li >> 7;
            int n  = li & 127;
            Bs[k][n] = W[(size_t)(kt + k) * NG + n0 + n];
        }
        __syncthreads();

        #pragma unroll
        for (int k = 0; k < BK; k++){
            u64 a[4];
            {
                const ulonglong2* ap = (const ulonglong2*)&Asd[k][tr * 4];
                ulonglong2 a01 = ap[0], a23 = ap[1];
                a[0] = a01.x; a[1] = a01.y; a[2] = a23.x; a[3] = a23.y;
            }
            u64 b[4];
            {
                const ulonglong2* bp = (const ulonglong2*)&Bs[k][tc * 8];
                ulonglong2 b01 = bp[0], b23 = bp[1];
                b[0] = b01.x; b[1] = b01.y; b[2] = b23.x; b[3] = b23.y;
            }
            #pragma unroll
            for (int i = 0; i < 4; i++){
                #pragma unroll
                for (int j = 0; j < 4; j++){
                    acc[i][j] = ffma2(a[i], b[j], acc[i][j]);
                }
            }
        }
        __syncthreads();
    }

    #pragma unroll
    for (int i = 0; i < 4; i++){
        size_t row = (size_t)d * NM + (size_t)(m0 + tr * 4 + i);
        u64* orow = (u64*)(g_xz + row * NG + n0 + tc * 8);
        orow[0] = acc[i][0]; orow[1] = acc[i][1]; orow[2] = acc[i][2]; orow[3] = acc[i][3];
    }
}

// ---------------------------------------------------------------------------
// Phase 2: bidirectional LSTM recurrence. One CTA = 8 sequences x one direction.
// Thread j owns hidden index j: accumulates gate pairs (i,f) and (g,o) as f32x2
// using the repacked U, applies activations itself (no smem transpose), and
// publishes h (duplicated pairs) into a double-buffered smem array.
// ---------------------------------------------------------------------------
__global__ __launch_bounds__(256, 1) void lstm_kernel(float* __restrict__ out)
{
    __shared__ u64 sh_h[2][NH][NSEQ];       // dup'd h pairs, double buffered (32 KB)
    __shared__ unsigned char sh_m[NSEQ][NT];

    const int tid  = threadIdx.x;
    const int d    = blockIdx.y;
    const int seq0 = blockIdx.x * NSEQ;

    float h_reg[NSEQ], c_reg[NSEQ];
    #pragma unroll
    for (int s = 0; s < NSEQ; s++){
        h_reg[s] = 0.f; c_reg[s] = 0.f;
        sh_h[0][tid][s] = 0ull;
    }
    for (int i = tid; i < NSEQ * NT; i += 256)
        (&sh_m[0][0])[i] = g_mask[(size_t)seq0 * NT + i];
    __syncthreads();

    const float* xzb = g_xz + (size_t)d * NM * NG + (size_t)seq0 * NT * NG;
    const ulonglong2* Upt = (const ulonglong2*)g_Upk + (size_t)d * NH * NH + tid;
    float* outb = out + (size_t)seq0 * NT * (2 * NH) + d * NH + tid;

    int rb = 0;
    for (int step = 0; step < NT; ++step){
        const int t = d ? (NT - 1 - step) : step;

        u64 aif[NSEQ], ago[NSEQ];
        #pragma unroll
        for (int s = 0; s < NSEQ; s++){
            const float* zr = xzb + ((size_t)s * NT + t) * NG;
            aif[s] = pack2(zr[tid],          zr[NH + tid]);
            ago[s] = pack2(zr[2 * NH + tid], zr[3 * NH + tid]);
        }

        #pragma unroll 8
        for (int k = 0; k < NH; k++){
            ulonglong2 uu = Upt[(size_t)k * NH];   // {(Ui,Uf),(Ug,Uo)} for (k, j=tid)
            const ulonglong2* hp = (const ulonglong2*)sh_h[rb][k];
            ulonglong2 ha = hp[0], hb = hp[1], hc = hp[2], hd4 = hp[3];
            u64 hh[NSEQ] = { ha.x, ha.y, hb.x, hb.y, hc.x, hc.y, hd4.x, hd4.y };
            #pragma unroll
            for (int s = 0; s < NSEQ; s++){
                aif[s] = ffma2(hh[s], uu.x, aif[s]);
                ago[s] = ffma2(hh[s], uu.y, ago[s]);
            }
        }

        #pragma unroll
        for (int s = 0; s < NSEQ; s++){
            float zi, zf, zg, zo;
            unpack2(aif[s], zi, zf);
            unpack2(ago[s], zg, zo);
            float ig = 1.f / (1.f + __expf(-zi));
            float fg = 1.f / (1.f + __expf(-zf));
            float gg = 1.f - 2.f / (__expf(2.f * zg) + 1.f);
            float og = 1.f / (1.f + __expf(-zo));
            float cn = fg * c_reg[s] + ig * gg;
            float hn = og * (1.f - 2.f / (__expf(2.f * cn) + 1.f));
            if (sh_m[s][t]){ c_reg[s] = cn; h_reg[s] = hn; }
            sh_h[rb ^ 1][tid][s] = pack2(h_reg[s], h_reg[s]);
            outb[((size_t)s * NT + t) * (2 * NH)] = h_reg[s];
        }
        __syncthreads();
        rb ^= 1;
    }
}

extern "C" void kernel_launch(void* const* d_in, const int* in_sizes, int n_in,
                              void* d_out, int out_size)
{
    const float*         facts = (const float*)d_in[0];
    const unsigned char* mask  = (const unsigned char*)d_in[1];
    const float*         Wf    = (const float*)d_in[2];
    const float*         Uf    = (const float*)d_in[3];
    const float*         bf    = (const float*)d_in[4];
    const float*         Wb    = (const float*)d_in[5];
    const float*         Ub    = (const float*)d_in[6];
    const float*         bb    = (const float*)d_in[7];
    float* out = (float*)d_out;

    repack_u_kernel<<<512, 256>>>(Uf, Ub);
    repack_mask_kernel<<<SEQS * NT / 256, 256>>>(mask);
    proj_kernel<<<dim3(NM / BM, 16), 256>>>(facts, Wf, bf, Wb, bb);
    lstm_kernel<<<dim3(SEQS / NSEQ, 2), 256>>>(out);
}

// round 3
// speedup vs baseline: 1.4246x; 1.4246x over previous
#include <cuda_runtime.h>
#include <cstdint>

typedef unsigned long long u64;

#define NB 16
#define NF 20
#define NT 128
#define ND 300
#define NH 256
#define NG 1024   // 4*H
#define SEQS 320  // NB*NF
#define NM 40960  // SEQS*NT
#define LNS 10    // sequences per lstm cluster (32 groups)

// Scratch: projection output (both dirs) 335 MB, repacked U 2 MB, mask 40 KB.
__device__ float g_xz[2ull * NM * NG];
__device__ u64 g_Upk2[2 * 2 * 256 * 256];   // [d][c][k][gp][jl] -> (gate0,gate1) pair
__device__ unsigned char g_mask[SEQS * NT];

__device__ __forceinline__ u64 pack2(float a, float b){
    u64 r; asm("mov.b64 %0, {%1, %2};" : "=l"(r) : "f"(a), "f"(b)); return r;
}
__device__ __forceinline__ void unpack2(u64 v, float& a, float& b){
    asm("mov.b64 {%0, %1}, %2;" : "=f"(a), "=f"(b) : "l"(v));
}
__device__ __forceinline__ u64 ffma2(u64 a, u64 b, u64 c){
    u64 d; asm("fma.rn.f32x2 %0, %1, %2, %3;" : "=l"(d) : "l"(a), "l"(b), "l"(c)); return d;
}
__device__ __forceinline__ uint32_t smem_u32(const void* p){
    uint32_t a; asm("{ .reg .u64 t; cvta.to.shared.u64 t, %1; cvt.u32.u64 %0, t; }" : "=r"(a) : "l"(p));
    return a;
}
__device__ __forceinline__ uint32_t mapa_u32(uint32_t addr, uint32_t rank){
    uint32_t r; asm("mapa.shared::cluster.u32 %0, %1, %2;" : "=r"(r) : "r"(addr), "r"(rank));
    return r;
}
__device__ __forceinline__ void st_cluster_u64(uint32_t addr, u64 v){
    asm volatile("st.shared::cluster.u64 [%0], %1;" :: "r"(addr), "l"(v) : "memory");
}
__device__ __forceinline__ void cluster_sync(){
    asm volatile("barrier.cluster.arrive.aligned;\n\tbarrier.cluster.wait.aligned;" ::: "memory");
}

// ---------------------------------------------------------------------------
// Repack U: g_Upk2[d][c][k][gp][jl] = (U[k][g0*256+j], U[k][(g0+1)*256+j])
// where j = c*128+jl, g0 = 2*gp. Gate pairs: gp0 -> (i,f), gp1 -> (g,o).
// ---------------------------------------------------------------------------
__global__ void repack_u_kernel(const float* __restrict__ Uf, const float* __restrict__ Ub)
{
    int idx = blockIdx.x * 256 + threadIdx.x;   // 0 .. 262143
    int jl = idx & 127;
    int gp = (idx >> 7) & 1;
    int k  = (idx >> 8) & 255;
    int c  = (idx >> 16) & 1;
    int d  = idx >> 17;
    const float* U = d ? Ub : Uf;
    int j  = c * 128 + jl;
    int g0 = gp * 2;
    g_Upk2[idx] = pack2(U[(size_t)k * NG + g0 * 256 + j],
                        U[(size_t)k * NG + g0 * 256 + 256 + j]);
}

// ---------------------------------------------------------------------------
// Canonicalize mask to u8. mask[0][0], mask[0][1] guaranteed true (len >= 64):
// byte0==0 -> float32; byte1!=0 -> uint8; else -> int32.
// ---------------------------------------------------------------------------
__global__ void repack_mask_kernel(const unsigned char* __restrict__ raw)
{
    int idx = blockIdx.x * 256 + threadIdx.x;
    unsigned char b0 = raw[0], b1 = raw[1];
    unsigned char v;
    if (b0 == 0)      v = (((const float*)raw)[idx] != 0.0f);
    else if (b1 != 0) v = (raw[idx] != 0);
    else              v = (((const int*)raw)[idx] != 0);
    g_mask[idx] = v;
}

// ---------------------------------------------------------------------------
// Phase 1: xz = x @ W + b.  M=40960, K=300, N=1024 per dir.
// BM=128, BN=128, BK=20, 256 threads, 8x8 thread tile, f32x2 FMAs.
// ---------------------------------------------------------------------------
#define BM 128
#define BN 128
#define BK 20
#define KT 300

__global__ __launch_bounds__(256, 2) void proj_kernel(
    const float* __restrict__ x,
    const float* __restrict__ Wf, const float* __restrict__ bf,
    const float* __restrict__ Wb, const float* __restrict__ bb)
{
    __shared__ u64  Asd[BK][BM + 2];   // A pre-duplicated (a,a) pairs, 20.8 KB
    __shared__ float Bs[BK][BN];       // 10 KB

    const int tid = threadIdx.x;
    const int m0  = blockIdx.x * BM;
    const int d   = blockIdx.y >> 3;
    const int n0  = (blockIdx.y & 7) * BN;
    const float* __restrict__ W    = d ? Wb : Wf;
    const float* __restrict__ bias = d ? bb : bf;
    const int tc = tid & 15;   // 8 cols each
    const int tr = tid >> 4;   // 8 rows each

    u64 acc[8][4];
    {
        const float* bp = bias + n0 + tc * 8;
        u64 b0 = pack2(bp[0], bp[1]);
        u64 b1 = pack2(bp[2], bp[3]);
        u64 b2 = pack2(bp[4], bp[5]);
        u64 b3 = pack2(bp[6], bp[7]);
        #pragma unroll
        for (int i = 0; i < 8; i++){ acc[i][0]=b0; acc[i][1]=b1; acc[i][2]=b2; acc[i][3]=b3; }
    }

    for (int kt = 0; kt < KT; kt += BK){
        #pragma unroll
        for (int i = 0; i < 10; i++){
            int li = tid + i * 256;
            int m  = li / BK;
            int k  = li % BK;
            float v = x[(size_t)(m0 + m) * ND + kt + k];
            Asd[k][m] = pack2(v, v);
        }
        #pragma unroll
        for (int i = 0; i < 10; i++){
            int li = tid + i * 256;
            int k  = li >> 7;
            int n  = li & 127;
            Bs[k][n] = W[(size_t)(kt + k) * NG + n0 + n];
        }
        __syncthreads();

        #pragma unroll
        for (int k = 0; k < BK; k++){
            u64 a[8];
            {
                const ulonglong2* ap = (const ulonglong2*)&Asd[k][tr * 8];
                ulonglong2 a01 = ap[0], a23 = ap[1], a45 = ap[2], a67 = ap[3];
                a[0]=a01.x; a[1]=a01.y; a[2]=a23.x; a[3]=a23.y;
                a[4]=a45.x; a[5]=a45.y; a[6]=a67.x; a[7]=a67.y;
            }
            u64 b[4];
            {
                const ulonglong2* bp = (const ulonglong2*)&Bs[k][tc * 8];
                ulonglong2 b01 = bp[0], b23 = bp[1];
                b[0]=b01.x; b[1]=b01.y; b[2]=b23.x; b[3]=b23.y;
            }
            #pragma unroll
            for (int i = 0; i < 8; i++){
                #pragma unroll
                for (int j = 0; j < 4; j++){
                    acc[i][j] = ffma2(a[i], b[j], acc[i][j]);
                }
            }
        }
        __syncthreads();
    }

    #pragma unroll
    for (int i = 0; i < 8; i++){
        size_t row = (size_t)d * NM + (size_t)(m0 + tr * 8 + i);
        ulonglong2* orow = (ulonglong2*)(g_xz + row * NG + n0 + tc * 8);
        ulonglong2 v0; v0.x = acc[i][0]; v0.y = acc[i][1];
        ulonglong2 v1; v1.x = acc[i][2]; v1.y = acc[i][3];
        orow[0] = v0; orow[1] = v1;
    }
}

// ---------------------------------------------------------------------------
// Phase 2: bidirectional LSTM recurrence, 2-CTA clusters.
// Cluster = LNS sequences x one direction; CTA c owns gate columns j in
// [c*128, c*128+128). Thread (jl, gp): gp0 accumulates (i,f), gp1 (g,o) for
// hidden index j = c*128+jl across LNS sequences. gp1 hands (g,o) to gp0 via
// smem; gp0 applies activations and publishes h (dup pairs) into BOTH CTAs'
// h buffers (own STS + peer DSMEM), then cluster.sync.
// Dynamic smem: sh_h[2][256][LNS] u64 (40960) + sh_zgo[128][LNS] u64 (10240)
//               + sh_m[LNS][128] u8 (1280) = 52480 B.
// ---------------------------------------------------------------------------
#define LSTM_SMEM (2*256*LNS*8 + 128*LNS*8 + LNS*NT)

__global__ __launch_bounds__(256, 1) __cluster_dims__(2, 1, 1)
void lstm_kernel(float* __restrict__ out)
{
    extern __shared__ __align__(16) char dsm[];
    u64* sh_h   = (u64*)dsm;                        // [2][256][LNS]
    u64* sh_zgo = (u64*)(dsm + 2*256*LNS*8);        // [128][LNS]
    unsigned char* sh_m = (unsigned char*)(dsm + 2*256*LNS*8 + 128*LNS*8); // [LNS][NT]

    const int tid = threadIdx.x;
    const int jl  = tid & 127;
    const int gp  = tid >> 7;
    const int c   = blockIdx.x;          // == cluster rank
    const int grp = blockIdx.y;
    const int d   = blockIdx.z;
    const int jg  = c * 128 + jl;
    const int seq0 = grp * LNS;

    uint32_t rank; asm("mov.u32 %0, %%cluster_ctarank;" : "=r"(rank));
    const uint32_t my_h   = smem_u32(sh_h);
    const uint32_t peer_h = mapa_u32(my_h, rank ^ 1);

    // init h buffer 0 to zero, load mask
    for (int i = tid; i < 256 * LNS; i += 256) sh_h[i] = 0ull;
    for (int i = tid; i < LNS * NT; i += 256)
        sh_m[i] = g_mask[(size_t)seq0 * NT + i];
    __syncthreads();

    float h_reg[LNS], c_reg[LNS];
    #pragma unroll
    for (int s = 0; s < LNS; s++){ h_reg[s] = 0.f; c_reg[s] = 0.f; }

    const float* xzb = g_xz + (size_t)d * NM * NG + (size_t)seq0 * NT * NG;
    const int col0 = gp ? 512 + jg : jg;      // gate pair columns: col0, col0+256
    const u64* Up = g_Upk2 + ((size_t)(d * 2 + c) * 256) * 256 + gp * 128 + jl;
    float* outb = out + (size_t)seq0 * NT * (2 * NH) + d * NH + jg;

    int rb = 0;
    for (int step = 0; step < NT; ++step){
        const int t = d ? (NT - 1 - step) : step;

        u64 acc[LNS];
        #pragma unroll
        for (int s = 0; s < LNS; s++){
            const float* zr = xzb + ((size_t)s * NT + t) * NG;
            acc[s] = pack2(zr[col0], zr[col0 + 256]);
        }

        const u64* hrow = sh_h + (size_t)rb * 256 * LNS;
        #pragma unroll 8
        for (int k = 0; k < 256; k++){
            u64 uu = Up[(size_t)k * 256];
            const ulonglong2* hp = (const ulonglong2*)(hrow + k * LNS);
            ulonglong2 h01 = hp[0], h23 = hp[1], h45 = hp[2], h67 = hp[3], h89 = hp[4];
            u64 hh[LNS] = { h01.x, h01.y, h23.x, h23.y, h45.x, h45.y, h67.x, h67.y, h89.x, h89.y };
            #pragma unroll
            for (int s = 0; s < LNS; s++)
                acc[s] = ffma2(hh[s], uu, acc[s]);
        }

        if (gp == 1){
            #pragma unroll
            for (int s = 0; s < LNS; s++) sh_zgo[jl * LNS + s] = acc[s];
        }
        __syncthreads();

        if (gp == 0){
            const int wb = rb ^ 1;
            #pragma unroll
            for (int s = 0; s < LNS; s++){
                float zi, zf, zg, zo;
                unpack2(acc[s], zi, zf);
                unpack2(sh_zgo[jl * LNS + s], zg, zo);
                float ig = 1.f / (1.f + __expf(-zi));
                float fg = 1.f / (1.f + __expf(-zf));
                float gg = 1.f - 2.f / (__expf(2.f * zg) + 1.f);
                float og = 1.f / (1.f + __expf(-zo));
                float cn = fg * c_reg[s] + ig * gg;
                float hn = og * (1.f - 2.f / (__expf(2.f * cn) + 1.f));
                if (sh_m[s * NT + t]){ c_reg[s] = cn; h_reg[s] = hn; }
                u64 hd = pack2(h_reg[s], h_reg[s]);
                uint32_t off = (uint32_t)(((wb * 256 + jg) * LNS + s) * 8);
                sh_h[(size_t)(wb * 256 + jg) * LNS + s] = hd;     // own buffer
                st_cluster_u64(peer_h + off, hd);                  // peer buffer
                outb[((size_t)s * NT + t) * (2 * NH)] = h_reg[s];
            }
        }
        cluster_sync();
        rb ^= 1;
    }
}

extern "C" void kernel_launch(void* const* d_in, const int* in_sizes, int n_in,
                              void* d_out, int out_size)
{
    const float*         facts = (const float*)d_in[0];
    const unsigned char* mask  = (const unsigned char*)d_in[1];
    const float*         Wf    = (const float*)d_in[2];
    const float*         Uf    = (const float*)d_in[3];
    const float*         bf    = (const float*)d_in[4];
    const float*         Wb    = (const float*)d_in[5];
    const float*         Ub    = (const float*)d_in[6];
    const float*         bb    = (const float*)d_in[7];
    float* out = (float*)d_out;

    cudaFuncSetAttribute(lstm_kernel, cudaFuncAttributeMaxDynamicSharedMemorySize, LSTM_SMEM);

    repack_u_kernel<<<1024, 256>>>(Uf, Ub);
    repack_mask_kernel<<<SEQS * NT / 256, 256>>>(mask);
    proj_kernel<<<dim3(NM / BM, 16), 256>>>(facts, Wf, bf, Wb, bb);
    lstm_kernel<<<dim3(2, SEQS / LNS, 2), 256, LSTM_SMEM>>>(out);
}

// round 4
// speedup vs baseline: 1.4411x; 1.0116x over previous
#include <cuda_runtime.h>
#include <cstdint>

typedef unsigned long long u64;

#define NB 16
#define NF 20
#define NT 128
#define ND 300
#define NH 256
#define NG 1024   // 4*H
#define SEQS 320  // NB*NF
#define NM 40960  // SEQS*NT
#define LNS 10    // sequences per lstm cluster (32 groups)

// Scratch: projection output (both dirs) 335 MB, repacked U 2 MB, mask 40 KB.
__device__ float g_xz[2ull * NM * NG];
__device__ u64 g_Upk4[2 * 2 * 128 * 256 * 2];  // [d][c][k2][col][kk] -> (gate0,gate1) pair
__device__ unsigned char g_mask[SEQS * NT];

__device__ __forceinline__ u64 pack2(float a, float b){
    u64 r; asm("mov.b64 %0, {%1, %2};" : "=l"(r) : "f"(a), "f"(b)); return r;
}
__device__ __forceinline__ void unpack2(u64 v, float& a, float& b){
    asm("mov.b64 {%0, %1}, %2;" : "=f"(a), "=f"(b) : "l"(v));
}
__device__ __forceinline__ u64 ffma2(u64 a, u64 b, u64 c){
    u64 d; asm("fma.rn.f32x2 %0, %1, %2, %3;" : "=l"(d) : "l"(a), "l"(b), "l"(c)); return d;
}
__device__ __forceinline__ u64 addf32x2(u64 a, u64 b){
    u64 d; asm("add.rn.f32x2 %0, %1, %2;" : "=l"(d) : "l"(a), "l"(b)); return d;
}
__device__ __forceinline__ uint32_t smem_u32(const void* p){
    uint32_t a; asm("{ .reg .u64 t; cvta.to.shared.u64 t, %1; cvt.u32.u64 %0, t; }" : "=r"(a) : "l"(p));
    return a;
}
__device__ __forceinline__ uint32_t mapa_u32(uint32_t addr, uint32_t rank){
    uint32_t r; asm("mapa.shared::cluster.u32 %0, %1, %2;" : "=r"(r) : "r"(addr), "r"(rank));
    return r;
}
__device__ __forceinline__ void st_cluster_u64(uint32_t addr, u64 v){
    asm volatile("st.shared::cluster.u64 [%0], %1;" :: "r"(addr), "l"(v) : "memory");
}
__device__ __forceinline__ void cluster_sync(){
    asm volatile("barrier.cluster.arrive.aligned;\n\tbarrier.cluster.wait.aligned;" ::: "memory");
}

// ---------------------------------------------------------------------------
// Repack U into k-paired gate-pair lanes:
// g_Upk4[(((d*2+c)*128 + k2)*256 + col)*2 + kk] = (U[k][g0*256+j], U[k][g0*256+256+j])
// with k = 2*k2+kk, col = gp*128+jl, j = c*128+jl, g0 = 2*gp.
// A thread's per-iteration LDG.128 fetches both k's of its column.
// ---------------------------------------------------------------------------
__global__ void repack_u_kernel(const float* __restrict__ Uf, const float* __restrict__ Ub)
{
    int idx = blockIdx.x * 256 + threadIdx.x;   // 0 .. 262143
    int kk  = idx & 1;
    int col = (idx >> 1) & 255;
    int k2  = (idx >> 9) & 127;
    int dc  = idx >> 16;
    int d = dc >> 1, c = dc & 1;
    int jl = col & 127, gp = col >> 7;
    int k  = 2 * k2 + kk;
    int j  = c * 128 + jl;
    int g0 = gp * 2;
    const float* U = d ? Ub : Uf;
    g_Upk4[idx] = pack2(U[(size_t)k * NG + g0 * 256 + j],
                        U[(size_t)k * NG + g0 * 256 + 256 + j]);
}

// ---------------------------------------------------------------------------
// Canonicalize mask to u8. mask[0][0], mask[0][1] guaranteed true (len >= 64):
// byte0==0 -> float32; byte1!=0 -> uint8; else -> int32.
// ---------------------------------------------------------------------------
__global__ void repack_mask_kernel(const unsigned char* __restrict__ raw)
{
    int idx = blockIdx.x * 256 + threadIdx.x;
    unsigned char b0 = raw[0], b1 = raw[1];
    unsigned char v;
    if (b0 == 0)      v = (((const float*)raw)[idx] != 0.0f);
    else if (b1 != 0) v = (raw[idx] != 0);
    else              v = (((const int*)raw)[idx] != 0);
    g_mask[idx] = v;
}

// ---------------------------------------------------------------------------
// Phase 1: xz = x @ W + b.  M=40960, K=300, N=1024 per dir.
// BM=128, BN=128, BK=20, 256 threads, 8x8 thread tile, f32x2 FMAs.
// ---------------------------------------------------------------------------
#define BM 128
#define BN 128
#define BK 20
#define KT 300

__global__ __launch_bounds__(256, 2) void proj_kernel(
    const float* __restrict__ x,
    const float* __restrict__ Wf, const float* __restrict__ bf,
    const float* __restrict__ Wb, const float* __restrict__ bb)
{
    __shared__ u64  Asd[BK][BM + 2];   // A pre-duplicated (a,a) pairs, 20.8 KB
    __shared__ float Bs[BK][BN];       // 10 KB

    const int tid = threadIdx.x;
    const int m0  = blockIdx.x * BM;
    const int d   = blockIdx.y >> 3;
    const int n0  = (blockIdx.y & 7) * BN;
    const float* __restrict__ W    = d ? Wb : Wf;
    const float* __restrict__ bias = d ? bb : bf;
    const int tc = tid & 15;   // 8 cols each
    const int tr = tid >> 4;   // 8 rows each

    u64 acc[8][4];
    {
        const float* bp = bias + n0 + tc * 8;
        u64 b0 = pack2(bp[0], bp[1]);
        u64 b1 = pack2(bp[2], bp[3]);
        u64 b2 = pack2(bp[4], bp[5]);
        u64 b3 = pack2(bp[6], bp[7]);
        #pragma unroll
        for (int i = 0; i < 8; i++){ acc[i][0]=b0; acc[i][1]=b1; acc[i][2]=b2; acc[i][3]=b3; }
    }

    for (int kt = 0; kt < KT; kt += BK){
        #pragma unroll
        for (int i = 0; i < 10; i++){
            int li = tid + i * 256;
            int m  = li / BK;
            int k  = li % BK;
            float v = x[(size_t)(m0 + m) * ND + kt + k];
            Asd[k][m] = pack2(v, v);
        }
        #pragma unroll
        for (int i = 0; i < 10; i++){
            int li = tid + i * 256;
            int k  = li >> 7;
            int n  = li & 127;
            Bs[k][n] = W[(size_t)(kt + k) * NG + n0 + n];
        }
        __syncthreads();

        #pragma unroll
        for (int k = 0; k < BK; k++){
            u64 a[8];
            {
                const ulonglong2* ap = (const ulonglong2*)&Asd[k][tr * 8];
                ulonglong2 a01 = ap[0], a23 = ap[1], a45 = ap[2], a67 = ap[3];
                a[0]=a01.x; a[1]=a01.y; a[2]=a23.x; a[3]=a23.y;
                a[4]=a45.x; a[5]=a45.y; a[6]=a67.x; a[7]=a67.y;
            }
            u64 b[4];
            {
                const ulonglong2* bp = (const ulonglong2*)&Bs[k][tc * 8];
                ulonglong2 b01 = bp[0], b23 = bp[1];
                b[0]=b01.x; b[1]=b01.y; b[2]=b23.x; b[3]=b23.y;
            }
            #pragma unroll
            for (int i = 0; i < 8; i++){
                #pragma unroll
                for (int j = 0; j < 4; j++){
                    acc[i][j] = ffma2(a[i], b[j], acc[i][j]);
                }
            }
        }
        __syncthreads();
    }

    #pragma unroll
    for (int i = 0; i < 8; i++){
        size_t row = (size_t)d * NM + (size_t)(m0 + tr * 8 + i);
        ulonglong2* orow = (ulonglong2*)(g_xz + row * NG + n0 + tc * 8);
        ulonglong2 v0; v0.x = acc[i][0]; v0.y = acc[i][1];
        ulonglong2 v1; v1.x = acc[i][2]; v1.y = acc[i][3];
        orow[0] = v0; orow[1] = v1;
    }
}

// ---------------------------------------------------------------------------
// Phase 2: bidirectional LSTM recurrence, 2-CTA clusters, 512 threads/CTA.
// Cluster = LNS sequences x one direction; CTA c owns gate columns [c*128,
// c*128+128). Thread (jl, gp, kh): gate-pair gp (0:(i,f), 1:(g,o)) for hidden
// index j = c*128+jl, accumulating over k-half kh. Per k2-iter: one LDG.128
// of paired U, 10 broadcast LDS.128 of h, 20 FFMA2. Step end: partials reduced
// via smem; gp0/kh0 threads apply activations, publish h into both CTAs'
// double-buffered h arrays (STS + DSMEM st.cluster), then cluster.sync.
// ---------------------------------------------------------------------------
#define LSTM_SMEM (2*256*LNS*8 + 3*128*LNS*8 + LNS*NT)

__global__ __launch_bounds__(512, 1) __cluster_dims__(2, 1, 1)
void lstm_kernel(float* __restrict__ out)
{
    extern __shared__ __align__(16) char dsm[];
    u64* sh_h    = (u64*)dsm;                          // [2][256][LNS]
    u64* sh_part = (u64*)(dsm + 2*256*LNS*8);          // [3][128][LNS]
    unsigned char* sh_m = (unsigned char*)(dsm + 2*256*LNS*8 + 3*128*LNS*8);

    const int tid = threadIdx.x;
    const int jl  = tid & 127;
    const int gp  = (tid >> 7) & 1;
    const int kh  = tid >> 8;
    const int c   = blockIdx.x;          // == cluster rank
    const int grp = blockIdx.y;
    const int d   = blockIdx.z;
    const int jg  = c * 128 + jl;
    const int seq0 = grp * LNS;

    uint32_t rank; asm("mov.u32 %0, %%cluster_ctarank;" : "=r"(rank));
    const uint32_t my_h   = smem_u32(sh_h);
    const uint32_t peer_h = mapa_u32(my_h, rank ^ 1);

    for (int i = tid; i < 256 * LNS; i += 512) sh_h[i] = 0ull;
    for (int i = tid; i < LNS * NT; i += 512)
        sh_m[i] = g_mask[(size_t)seq0 * NT + i];
    __syncthreads();

    float h_reg[LNS], c_reg[LNS];
    #pragma unroll
    for (int s = 0; s < LNS; s++){ h_reg[s] = 0.f; c_reg[s] = 0.f; }

    const float* xzb = g_xz + (size_t)d * NM * NG + (size_t)seq0 * NT * NG;
    const int col0 = gp ? 512 + jg : jg;      // gate-pair columns: col0, col0+256
    const ulonglong2* Up = (const ulonglong2*)g_Upk4
                         + ((size_t)(d * 2 + c) * 128 + kh * 64) * 256 + (gp * 128 + jl);
    float* outb = out + (size_t)seq0 * NT * (2 * NH) + d * NH + jg;
    const int pi = gp * 2 + kh;   // 0: finalizer; 1..3: partial writers

    int rb = 0;
    for (int step = 0; step < NT; ++step){
        const int t = d ? (NT - 1 - step) : step;

        u64 acc[LNS];
        if (kh == 0){
            #pragma unroll
            for (int s = 0; s < LNS; s++){
                const float* zr = xzb + ((size_t)s * NT + t) * NG;
                acc[s] = pack2(zr[col0], zr[col0 + 256]);
            }
        } else {
            #pragma unroll
            for (int s = 0; s < LNS; s++) acc[s] = 0ull;
        }

        const u64* hrow = sh_h + (size_t)rb * 256 * LNS + kh * 128 * LNS;
        #pragma unroll 2
        for (int k2 = 0; k2 < 64; k2++){
            ulonglong2 U2 = Up[(size_t)k2 * 256];      // (k=2k2, k=2k2+1) pairs
            const ulonglong2* hp = (const ulonglong2*)(hrow + k2 * 2 * LNS);
            ulonglong2 p0 = hp[0], p1 = hp[1], p2 = hp[2], p3 = hp[3], p4 = hp[4];
            ulonglong2 q0 = hp[5], q1 = hp[6], q2 = hp[7], q3 = hp[8], q4 = hp[9];
            u64 h0[LNS] = { p0.x, p0.y, p1.x, p1.y, p2.x, p2.y, p3.x, p3.y, p4.x, p4.y };
            u64 h1[LNS] = { q0.x, q0.y, q1.x, q1.y, q2.x, q2.y, q3.x, q3.y, q4.x, q4.y };
            #pragma unroll
            for (int s = 0; s < LNS; s++){
                acc[s] = ffma2(h0[s], U2.x, acc[s]);
                acc[s] = ffma2(h1[s], U2.y, acc[s]);
            }
        }

        if (pi > 0){
            u64* pp = sh_part + ((size_t)(pi - 1) * 128 + jl) * LNS;
            #pragma unroll
            for (int s = 0; s < LNS; s++) pp[s] = acc[s];
        }
        __syncthreads();

        if (pi == 0){
            const int wb = rb ^ 1;
            const u64* r0 = sh_part + (size_t)jl * LNS;                 // gp0,kh1
            const u64* r1 = sh_part + ((size_t)128 + jl) * LNS;         // gp1,kh0
            const u64* r2 = sh_part + ((size_t)256 + jl) * LNS;         // gp1,kh1
            #pragma unroll
            for (int s = 0; s < LNS; s++){
                u64 zif = addf32x2(acc[s], r0[s]);
                u64 zgo = addf32x2(r1[s], r2[s]);
                float zi, zf, zg, zo;
                unpack2(zif, zi, zf);
                unpack2(zgo, zg, zo);
                float ig = 1.f / (1.f + __expf(-zi));
                float fg = 1.f / (1.f + __expf(-zf));
                float gg = 1.f - 2.f / (__expf(2.f * zg) + 1.f);
                float og = 1.f / (1.f + __expf(-zo));
                float cn = fg * c_reg[s] + ig * gg;
                float hn = og * (1.f - 2.f / (__expf(2.f * cn) + 1.f));
                if (sh_m[s * NT + t]){ c_reg[s] = cn; h_reg[s] = hn; }
                u64 hd = pack2(h_reg[s], h_reg[s]);
                size_t hidx = (size_t)wb * 256 * LNS + (size_t)jg * LNS + s;
                sh_h[hidx] = hd;                               // own buffer
                st_cluster_u64(peer_h + (uint32_t)(hidx * 8), hd);  // peer buffer
                outb[((size_t)s * NT + t) * (2 * NH)] = h_reg[s];
            }
        }
        cluster_sync();
        rb ^= 1;
    }
}

extern "C" void kernel_launch(void* const* d_in, const int* in_sizes, int n_in,
                              void* d_out, int out_size)
{
    const float*         facts = (const float*)d_in[0];
    const unsigned char* mask  = (const unsigned char*)d_in[1];
    const float*         Wf    = (const float*)d_in[2];
    const float*         Uf    = (const float*)d_in[3];
    const float*         bf    = (const float*)d_in[4];
    const float*         Wb    = (const float*)d_in[5];
    const float*         Ub    = (const float*)d_in[6];
    const float*         bb    = (const float*)d_in[7];
    float* out = (float*)d_out;

    cudaFuncSetAttribute(lstm_kernel, cudaFuncAttributeMaxDynamicSharedMemorySize, LSTM_SMEM);

    repack_u_kernel<<<1024, 256>>>(Uf, Ub);
    repack_mask_kernel<<<SEQS * NT / 256, 256>>>(mask);
    proj_kernel<<<dim3(NM / BM, 16), 256>>>(facts, Wf, bf, Wb, bb);
    lstm_kernel<<<dim3(2, SEQS / LNS, 2), 512, LSTM_SMEM>>>(out);
}

// round 5
// speedup vs baseline: 1.4593x; 1.0126x over previous
#include <cuda_runtime.h>
#include <cstdint>

typedef unsigned long long u64;

#define NB 16
#define NF 20
#define NT 128
#define ND 300
#define NH 256
#define NG 1024   // 4*H
#define SEQS 320  // NB*NF
#define NM 40960  // SEQS*NT
#define LNS 10    // sequences per lstm cluster (32 groups)

// Scratch: projection output (both dirs) 335 MB, repacked U 2 MB, mask 40 KB.
__device__ float g_xz[2ull * NM * NG];
__device__ u64 g_Upk4[2 * 2 * 128 * 256 * 2];  // [d][c][k2][col][kk] -> (gate0,gate1) pair
__device__ unsigned char g_mask[SEQS * NT];

__device__ __forceinline__ u64 pack2(float a, float b){
    u64 r; asm("mov.b64 %0, {%1, %2};" : "=l"(r) : "f"(a), "f"(b)); return r;
}
__device__ __forceinline__ void unpack2(u64 v, float& a, float& b){
    asm("mov.b64 {%0, %1}, %2;" : "=f"(a), "=f"(b) : "l"(v));
}
__device__ __forceinline__ u64 ffma2(u64 a, u64 b, u64 c){
    u64 d; asm("fma.rn.f32x2 %0, %1, %2, %3;" : "=l"(d) : "l"(a), "l"(b), "l"(c)); return d;
}
__device__ __forceinline__ u64 addf32x2(u64 a, u64 b){
    u64 d; asm("add.rn.f32x2 %0, %1, %2;" : "=l"(d) : "l"(a), "l"(b)); return d;
}
__device__ __forceinline__ uint32_t smem_u32(const void* p){
    uint32_t a; asm("{ .reg .u64 t; cvta.to.shared.u64 t, %1; cvt.u32.u64 %0, t; }" : "=r"(a) : "l"(p));
    return a;
}
__device__ __forceinline__ uint32_t mapa_u32(uint32_t addr, uint32_t rank){
    uint32_t r; asm("mapa.shared::cluster.u32 %0, %1, %2;" : "=r"(r) : "r"(addr), "r"(rank));
    return r;
}
__device__ __forceinline__ void st_cluster_u64(uint32_t addr, u64 v){
    asm volatile("st.shared::cluster.u64 [%0], %1;" :: "r"(addr), "l"(v) : "memory");
}
__device__ __forceinline__ void cluster_sync(){
    asm volatile("barrier.cluster.arrive.aligned;\n\tbarrier.cluster.wait.aligned;" ::: "memory");
}
__device__ __forceinline__ void cp_async16(uint32_t sdst, const void* gsrc){
    asm volatile("cp.async.ca.shared.global [%0], [%1], 16;" :: "r"(sdst), "l"(gsrc) : "memory");
}
__device__ __forceinline__ void cp_async_commit(){
    asm volatile("cp.async.commit_group;" ::: "memory");
}
__device__ __forceinline__ void cp_async_wait0(){
    asm volatile("cp.async.wait_group 0;" ::: "memory");
}

// ---------------------------------------------------------------------------
// Repack U into k-paired gate-pair lanes:
// g_Upk4[(((d*2+c)*128 + k2)*256 + col)*2 + kk] = (U[k][g0*256+j], U[k][g0*256+256+j])
// with k = 2*k2+kk, col = gp*128+jl, j = c*128+jl, g0 = 2*gp.
// ---------------------------------------------------------------------------
__global__ void repack_u_kernel(const float* __restrict__ Uf, const float* __restrict__ Ub)
{
    int idx = blockIdx.x * 256 + threadIdx.x;   // 0 .. 262143
    int kk  = idx & 1;
    int col = (idx >> 1) & 255;
    int k2  = (idx >> 9) & 127;
    int dc  = idx >> 16;
    int d = dc >> 1, c = dc & 1;
    int jl = col & 127, gp = col >> 7;
    int k  = 2 * k2 + kk;
    int j  = c * 128 + jl;
    int g0 = gp * 2;
    const float* U = d ? Ub : Uf;
    g_Upk4[idx] = pack2(U[(size_t)k * NG + g0 * 256 + j],
                        U[(size_t)k * NG + g0 * 256 + 256 + j]);
}

// ---------------------------------------------------------------------------
// Canonicalize mask to u8. mask[0][0], mask[0][1] guaranteed true (len >= 64):
// byte0==0 -> float32; byte1!=0 -> uint8; else -> int32.
// ---------------------------------------------------------------------------
__global__ void repack_mask_kernel(const unsigned char* __restrict__ raw)
{
    int idx = blockIdx.x * 256 + threadIdx.x;
    unsigned char b0 = raw[0], b1 = raw[1];
    unsigned char v;
    if (b0 == 0)      v = (((const float*)raw)[idx] != 0.0f);
    else if (b1 != 0) v = (raw[idx] != 0);
    else              v = (((const int*)raw)[idx] != 0);
    g_mask[idx] = v;
}

// ---------------------------------------------------------------------------
// Phase 1: xz = x @ W + b.  M=40960, K=300, N=1024 per dir.
// BM=128, BN=128, BK=20, 256 threads, 8x8 thread tile, f32x2 FMAs.
// ---------------------------------------------------------------------------
#define BM 128
#define BN 128
#define BK 20
#define KT 300

__global__ __launch_bounds__(256, 2) void proj_kernel(
    const float* __restrict__ x,
    const float* __restrict__ Wf, const float* __restrict__ bf,
    const float* __restrict__ Wb, const float* __restrict__ bb)
{
    __shared__ u64  Asd[BK][BM + 2];
    __shared__ float Bs[BK][BN];

    const int tid = threadIdx.x;
    const int m0  = blockIdx.x * BM;
    const int d   = blockIdx.y >> 3;
    const int n0  = (blockIdx.y & 7) * BN;
    const float* __restrict__ W    = d ? Wb : Wf;
    const float* __restrict__ bias = d ? bb : bf;
    const int tc = tid & 15;
    const int tr = tid >> 4;

    u64 acc[8][4];
    {
        const float* bp = bias + n0 + tc * 8;
        u64 b0 = pack2(bp[0], bp[1]);
        u64 b1 = pack2(bp[2], bp[3]);
        u64 b2 = pack2(bp[4], bp[5]);
        u64 b3 = pack2(bp[6], bp[7]);
        #pragma unroll
        for (int i = 0; i < 8; i++){ acc[i][0]=b0; acc[i][1]=b1; acc[i][2]=b2; acc[i][3]=b3; }
    }

    for (int kt = 0; kt < KT; kt += BK){
        #pragma unroll
        for (int i = 0; i < 10; i++){
            int li = tid + i * 256;
            int m  = li / BK;
            int k  = li % BK;
            float v = x[(size_t)(m0 + m) * ND + kt + k];
            Asd[k][m] = pack2(v, v);
        }
        #pragma unroll
        for (int i = 0; i < 10; i++){
            int li = tid + i * 256;
            int k  = li >> 7;
            int n  = li & 127;
            Bs[k][n] = W[(size_t)(kt + k) * NG + n0 + n];
        }
        __syncthreads();

        #pragma unroll
        for (int k = 0; k < BK; k++){
            u64 a[8];
            {
                const ulonglong2* ap = (const ulonglong2*)&Asd[k][tr * 8];
                ulonglong2 a01 = ap[0], a23 = ap[1], a45 = ap[2], a67 = ap[3];
                a[0]=a01.x; a[1]=a01.y; a[2]=a23.x; a[3]=a23.y;
                a[4]=a45.x; a[5]=a45.y; a[6]=a67.x; a[7]=a67.y;
            }
            u64 b[4];
            {
                const ulonglong2* bp = (const ulonglong2*)&Bs[k][tc * 8];
                ulonglong2 b01 = bp[0], b23 = bp[1];
                b[0]=b01.x; b[1]=b01.y; b[2]=b23.x; b[3]=b23.y;
            }
            #pragma unroll
            for (int i = 0; i < 8; i++){
                #pragma unroll
                for (int j = 0; j < 4; j++){
                    acc[i][j] = ffma2(a[i], b[j], acc[i][j]);
                }
            }
        }
        __syncthreads();
    }

    #pragma unroll
    for (int i = 0; i < 8; i++){
        size_t row = (size_t)d * NM + (size_t)(m0 + tr * 8 + i);
        ulonglong2* orow = (ulonglong2*)(g_xz + row * NG + n0 + tc * 8);
        ulonglong2 v0; v0.x = acc[i][0]; v0.y = acc[i][1];
        ulonglong2 v1; v1.x = acc[i][2]; v1.y = acc[i][3];
        orow[0] = v0; orow[1] = v1;
    }
}

// ---------------------------------------------------------------------------
// Phase 2: LSTM recurrence, 2-CTA clusters, 512 threads/CTA.
// Thread (jl, gp, kh). Per step: acc-init from cp.async-staged xz (kh0) or 0;
// distance-2 pipelined U k-loop; ALL groups write partials; group pi
// finalizes its 2-3 sequences (state-partitioned); h published to both CTAs.
// smem: h 2x256x10 u64 (40960) + part 4x128x10 u64 (40960)
//     + xz 2x10x512 f32 (40960) + mask 1280 = 124160 B.
// ---------------------------------------------------------------------------
#define XZS 512
#define LSTM_SMEM (2*256*LNS*8 + 4*128*LNS*8 + 2*LNS*XZS*4 + LNS*NT)

__global__ __launch_bounds__(512, 1) __cluster_dims__(2, 1, 1)
void lstm_kernel(float* __restrict__ out)
{
    extern __shared__ __align__(16) char dsm[];
    u64*   sh_h    = (u64*)dsm;                                   // [2][256][LNS]
    u64*   sh_part = (u64*)(dsm + 2*256*LNS*8);                   // [4][128][LNS]
    float* sh_xz   = (float*)(dsm + 2*256*LNS*8 + 4*128*LNS*8);   // [2][LNS][XZS]
    unsigned char* sh_m = (unsigned char*)(dsm + 2*256*LNS*8 + 4*128*LNS*8 + 2*LNS*XZS*4);

    const int tid = threadIdx.x;
    const int jl  = tid & 127;
    const int gp  = (tid >> 7) & 1;
    const int kh  = tid >> 8;
    const int pi  = gp * 2 + kh;
    const int c   = blockIdx.x;          // == cluster rank
    const int grp = blockIdx.y;
    const int d   = blockIdx.z;
    const int jg  = c * 128 + jl;
    const int seq0 = grp * LNS;

    uint32_t rank; asm("mov.u32 %0, %%cluster_ctarank;" : "=r"(rank));
    const uint32_t my_h   = smem_u32(sh_h);
    const uint32_t peer_h = mapa_u32(my_h, rank ^ 1);
    const uint32_t xz_s32 = smem_u32(sh_xz);

    for (int i = tid; i < 256 * LNS; i += 512) sh_h[i] = 0ull;
    for (int i = tid; i < LNS * NT; i += 512)
        sh_m[i] = g_mask[(size_t)seq0 * NT + i];

    const float* xzb = g_xz + (size_t)d * NM * NG + (size_t)seq0 * NT * NG;

    // Prime xz stage for step 0 into buffer 0.
    {
        const int t0 = d ? (NT - 1) : 0;
        #pragma unroll
        for (int i = tid; i < 1280; i += 512){
            int s = i >> 7;
            int o = i & 127;
            int gcol = ((o >> 5) << 8) + c * 128 + ((o & 31) << 2);
            const float* src = xzb + ((size_t)s * NT + t0) * NG + gcol;
            uint32_t dst = xz_s32 + (uint32_t)((s * XZS + (o >> 5) * 128 + ((o & 31) << 2)) * 4);
            cp_async16(dst, src);
        }
        cp_async_commit();
        cp_async_wait0();
    }
    __syncthreads();

    float h_reg[3], c_reg[3];
    #pragma unroll
    for (int i = 0; i < 3; i++){ h_reg[i] = 0.f; c_reg[i] = 0.f; }
    const int scnt = (pi < 2) ? 3 : 2;               // seqs this group finalizes
    const int sbase = (pi < 2) ? pi * 3 : 6 + (pi - 2) * 2;

    const ulonglong2* Up = (const ulonglong2*)g_Upk4
                         + ((size_t)(d * 2 + c) * 128 + kh * 64) * 256 + (gp * 128 + jl);
    float* outb = out + (size_t)seq0 * NT * (2 * NH) + d * NH + jg;

    int rb = 0;   // h read buffer; also xz read buffer
    for (int step = 0; step < NT; ++step){
        const int t = d ? (NT - 1 - step) : step;

        // acc init: kh0 from staged xz, kh1 zero.
        u64 acc[LNS];
        if (kh == 0){
            const float* xs = sh_xz + (size_t)rb * LNS * XZS + gp * 256 + jl;
            #pragma unroll
            for (int s = 0; s < LNS; s++)
                acc[s] = pack2(xs[s * XZS], xs[s * XZS + 128]);
        } else {
            #pragma unroll
            for (int s = 0; s < LNS; s++) acc[s] = 0ull;
        }

        // Kick xz prefetch for the next step into buffer rb^1.
        if (step < NT - 1){
            const int tn = d ? (NT - 2 - step) : (step + 1);
            #pragma unroll
            for (int i = tid; i < 1280; i += 512){
                int s = i >> 7;
                int o = i & 127;
                int gcol = ((o >> 5) << 8) + c * 128 + ((o & 31) << 2);
                const float* src = xzb + ((size_t)s * NT + tn) * NG + gcol;
                uint32_t dst = xz_s32 + (uint32_t)((((rb ^ 1) * LNS + s) * XZS
                                   + (o >> 5) * 128 + ((o & 31) << 2)) * 4);
                cp_async16(dst, src);
            }
        }
        cp_async_commit();

        // Main k-loop: distance-2 pipelined U stream.
        const u64* hrow = sh_h + (size_t)rb * 256 * LNS + kh * 128 * LNS;
        ulonglong2 Ucur = Up[0];
        ulonglong2 Unxt = Up[256];
        #pragma unroll 2
        for (int k2 = 0; k2 < 64; k2++){
            ulonglong2 Uuse = Ucur;
            Ucur = Unxt;
            if (k2 < 62) Unxt = Up[(size_t)(k2 + 2) * 256];
            const ulonglong2* hp = (const ulonglong2*)(hrow + k2 * 2 * LNS);
            ulonglong2 p0 = hp[0], p1 = hp[1], p2 = hp[2], p3 = hp[3], p4 = hp[4];
            ulonglong2 q0 = hp[5], q1 = hp[6], q2 = hp[7], q3 = hp[8], q4 = hp[9];
            u64 h0[LNS] = { p0.x, p0.y, p1.x, p1.y, p2.x, p2.y, p3.x, p3.y, p4.x, p4.y };
            u64 h1[LNS] = { q0.x, q0.y, q1.x, q1.y, q2.x, q2.y, q3.x, q3.y, q4.x, q4.y };
            #pragma unroll
            for (int s = 0; s < LNS; s++){
                acc[s] = ffma2(h0[s], Uuse.x, acc[s]);
                acc[s] = ffma2(h1[s], Uuse.y, acc[s]);
            }
        }

        // All groups write partials.
        {
            u64* pp = sh_part + ((size_t)pi * 128 + jl) * LNS;
            #pragma unroll
            for (int s = 0; s < LNS; s++) pp[s] = acc[s];
        }
        __syncthreads();

        // Distributed finalize: group pi handles seqs [sbase, sbase+scnt).
        {
            const int wb = rb ^ 1;
            const u64* p0 = sh_part + (size_t)jl * LNS;            // gp0 kh0
            const u64* p1 = sh_part + ((size_t)128 + jl) * LNS;    // gp0 kh1
            const u64* p2 = sh_part + ((size_t)256 + jl) * LNS;    // gp1 kh0
            const u64* p3 = sh_part + ((size_t)384 + jl) * LNS;    // gp1 kh1
            #pragma unroll
            for (int si = 0; si < 3; si++){
                if (si < scnt){
                    const int s = sbase + si;
                    u64 zif = addf32x2(p0[s], p1[s]);
                    u64 zgo = addf32x2(p2[s], p3[s]);
                    float zi, zf, zg, zo;
                    unpack2(zif, zi, zf);
                    unpack2(zgo, zg, zo);
                    float ig = 1.f / (1.f + __expf(-zi));
                    float fg = 1.f / (1.f + __expf(-zf));
                    float gg = 1.f - 2.f / (__expf(2.f * zg) + 1.f);
                    float og = 1.f / (1.f + __expf(-zo));
                    float cn = fg * c_reg[si] + ig * gg;
                    float hn = og * (1.f - 2.f / (__expf(2.f * cn) + 1.f));
                    if (sh_m[s * NT + t]){ c_reg[si] = cn; h_reg[si] = hn; }
                    u64 hd = pack2(h_reg[si], h_reg[si]);
                    size_t hidx = (size_t)wb * 256 * LNS + (size_t)jg * LNS + s;
                    sh_h[hidx] = hd;
                    st_cluster_u64(peer_h + (uint32_t)(hidx * 8), hd);
                    outb[((size_t)s * NT + t) * (2 * NH)] = h_reg[si];
                }
            }
        }
        cp_async_wait0();
        cluster_sync();
        rb ^= 1;
    }
}

extern "C" void kernel_launch(void* const* d_in, const int* in_sizes, int n_in,
                              void* d_out, int out_size)
{
    const float*         facts = (const float*)d_in[0];
    const unsigned char* mask  = (const unsigned char*)d_in[1];
    const float*         Wf    = (const float*)d_in[2];
    const float*         Uf    = (const float*)d_in[3];
    const float*         bf    = (const float*)d_in[4];
    const float*         Wb    = (const float*)d_in[5];
    const float*         Ub    = (const float*)d_in[6];
    const float*         bb    = (const float*)d_in[7];
    float* out = (float*)d_out;

    cudaFuncSetAttribute(lstm_kernel, cudaFuncAttributeMaxDynamicSharedMemorySize, LSTM_SMEM);

    repack_u_kernel<<<1024, 256>>>(Uf, Ub);
    repack_mask_kernel<<<SEQS * NT / 256, 256>>>(mask);
    proj_kernel<<<dim3(NM / BM, 16), 256>>>(facts, Wf, bf, Wb, bb);
    lstm_kernel<<<dim3(2, SEQS / LNS, 2), 512, LSTM_SMEM>>>(out);
}

// round 6
// speedup vs baseline: 1.5500x; 1.0622x over previous
#include <cuda_runtime.h>
#include <cstdint>

typedef unsigned long long u64;

#define NB 16
#define NF 20
#define NT 128
#define ND 300
#define NH 256
#define NG 1024   // 4*H
#define SEQS 320  // NB*NF
#define NM 40960  // SEQS*NT
#define LNS 10    // sequences per lstm cluster (32 groups)

// Scratch: projection output (both dirs) 335 MB, repacked U 2 MB, mask 40 KB.
__device__ float g_xz[2ull * NM * NG];
// U layout for the lstm: [d][c][k2][half][q][lane][jlq] u64, q = kk*2+gp,
// cg = half*32+lane, col j = c*128 + 2*cg + jlq, pair = (gate g0, gate g0+1).
__device__ u64 g_U6[2 * 2 * 128 * 2 * 4 * 32 * 2];
__device__ unsigned char g_mask[SEQS * NT];

__device__ __forceinline__ u64 pack2(float a, float b){
    u64 r; asm("mov.b64 %0, {%1, %2};" : "=l"(r) : "f"(a), "f"(b)); return r;
}
__device__ __forceinline__ void unpack2(u64 v, float& a, float& b){
    asm("mov.b64 {%0, %1}, %2;" : "=f"(a), "=f"(b) : "l"(v));
}
__device__ __forceinline__ u64 ffma2(u64 a, u64 b, u64 c){
    u64 d; asm("fma.rn.f32x2 %0, %1, %2, %3;" : "=l"(d) : "l"(a), "l"(b), "l"(c)); return d;
}
__device__ __forceinline__ u64 addf32x2(u64 a, u64 b){
    u64 d; asm("add.rn.f32x2 %0, %1, %2;" : "=l"(d) : "l"(a), "l"(b)); return d;
}
__device__ __forceinline__ uint32_t smem_u32(const void* p){
    uint32_t a; asm("{ .reg .u64 t; cvta.to.shared.u64 t, %1; cvt.u32.u64 %0, t; }" : "=r"(a) : "l"(p));
    return a;
}
__device__ __forceinline__ uint32_t mapa_u32(uint32_t addr, uint32_t rank){
    uint32_t r; asm("mapa.shared::cluster.u32 %0, %1, %2;" : "=r"(r) : "r"(addr), "r"(rank));
    return r;
}
__device__ __forceinline__ void st_cluster_u64(uint32_t addr, u64 v){
    asm volatile("st.shared::cluster.u64 [%0], %1;" :: "r"(addr), "l"(v) : "memory");
}
__device__ __forceinline__ void cluster_sync(){
    asm volatile("barrier.cluster.arrive.aligned;\n\tbarrier.cluster.wait.aligned;" ::: "memory");
}
__device__ __forceinline__ void cp_async16(uint32_t sdst, const void* gsrc){
    asm volatile("cp.async.ca.shared.global [%0], [%1], 16;" :: "r"(sdst), "l"(gsrc) : "memory");
}
__device__ __forceinline__ void cp_async_commit(){
    asm volatile("cp.async.commit_group;" ::: "memory");
}
__device__ __forceinline__ void cp_async_wait0(){
    asm volatile("cp.async.wait_group 0;" ::: "memory");
}

// ---------------------------------------------------------------------------
// Repack U into the warp-coalesced 4-col layout described above.
// ---------------------------------------------------------------------------
__global__ void repack_u_kernel(const float* __restrict__ Uf, const float* __restrict__ Ub)
{
    int idx = blockIdx.x * 256 + threadIdx.x;   // 0 .. 262143 (u64 units)
    int w    = idx & 1;            // jlq
    int lane = (idx >> 1) & 31;
    int q    = (idx >> 6) & 3;     // kk*2 + gp
    int half = (idx >> 8) & 1;
    int k2   = (idx >> 9) & 127;
    int dc   = idx >> 16;
    int d = dc >> 1, c = dc & 1;
    int kk = q >> 1, gp = q & 1;
    int cg = half * 32 + lane;
    int k  = 2 * k2 + kk;
    int j  = c * 128 + 2 * cg + w;
    int g0 = gp * 2;
    const float* U = d ? Ub : Uf;
    g_U6[idx] = pack2(U[(size_t)k * NG + g0 * 256 + j],
                      U[(size_t)k * NG + g0 * 256 + 256 + j]);
}

// ---------------------------------------------------------------------------
// Canonicalize mask to u8. mask[0][0], mask[0][1] guaranteed true (len >= 64):
// byte0==0 -> float32; byte1!=0 -> uint8; else -> int32.
// ---------------------------------------------------------------------------
__global__ void repack_mask_kernel(const unsigned char* __restrict__ raw)
{
    int idx = blockIdx.x * 256 + threadIdx.x;
    unsigned char b0 = raw[0], b1 = raw[1];
    unsigned char v;
    if (b0 == 0)      v = (((const float*)raw)[idx] != 0.0f);
    else if (b1 != 0) v = (raw[idx] != 0);
    else              v = (((const int*)raw)[idx] != 0);
    g_mask[idx] = v;
}

// ---------------------------------------------------------------------------
// Phase 1: xz = x @ W + b.  M=40960, K=300, N=1024 per dir. (unchanged)
// ---------------------------------------------------------------------------
#define BM 128
#define BN 128
#define BK 20
#define KT 300

__global__ __launch_bounds__(256, 2) void proj_kernel(
    const float* __restrict__ x,
    const float* __restrict__ Wf, const float* __restrict__ bf,
    const float* __restrict__ Wb, const float* __restrict__ bb)
{
    __shared__ u64  Asd[BK][BM + 2];
    __shared__ float Bs[BK][BN];

    const int tid = threadIdx.x;
    const int m0  = blockIdx.x * BM;
    const int d   = blockIdx.y >> 3;
    const int n0  = (blockIdx.y & 7) * BN;
    const float* __restrict__ W    = d ? Wb : Wf;
    const float* __restrict__ bias = d ? bb : bf;
    const int tc = tid & 15;
    const int tr = tid >> 4;

    u64 acc[8][4];
    {
        const float* bp = bias + n0 + tc * 8;
        u64 b0 = pack2(bp[0], bp[1]);
        u64 b1 = pack2(bp[2], bp[3]);
        u64 b2 = pack2(bp[4], bp[5]);
        u64 b3 = pack2(bp[6], bp[7]);
        #pragma unroll
        for (int i = 0; i < 8; i++){ acc[i][0]=b0; acc[i][1]=b1; acc[i][2]=b2; acc[i][3]=b3; }
    }

    for (int kt = 0; kt < KT; kt += BK){
        #pragma unroll
        for (int i = 0; i < 10; i++){
            int li = tid + i * 256;
            int m  = li / BK;
            int k  = li % BK;
            float v = x[(size_t)(m0 + m) * ND + kt + k];
            Asd[k][m] = pack2(v, v);
        }
        #pragma unroll
        for (int i = 0; i < 10; i++){
            int li = tid + i * 256;
            int k  = li >> 7;
            int n  = li & 127;
            Bs[k][n] = W[(size_t)(kt + k) * NG + n0 + n];
        }
        __syncthreads();

        #pragma unroll
        for (int k = 0; k < BK; k++){
            u64 a[8];
            {
                const ulonglong2* ap = (const ulonglong2*)&Asd[k][tr * 8];
                ulonglong2 a01 = ap[0], a23 = ap[1], a45 = ap[2], a67 = ap[3];
                a[0]=a01.x; a[1]=a01.y; a[2]=a23.x; a[3]=a23.y;
                a[4]=a45.x; a[5]=a45.y; a[6]=a67.x; a[7]=a67.y;
            }
            u64 b[4];
            {
                const ulonglong2* bp = (const ulonglong2*)&Bs[k][tc * 8];
                ulonglong2 b01 = bp[0], b23 = bp[1];
                b[0]=b01.x; b[1]=b01.y; b[2]=b23.x; b[3]=b23.y;
            }
            #pragma unroll
            for (int i = 0; i < 8; i++){
                #pragma unroll
                for (int j = 0; j < 4; j++){
                    acc[i][j] = ffma2(a[i], b[j], acc[i][j]);
                }
            }
        }
        __syncthreads();
    }

    #pragma unroll
    for (int i = 0; i < 8; i++){
        size_t row = (size_t)d * NM + (size_t)(m0 + tr * 8 + i);
        ulonglong2* orow = (ulonglong2*)(g_xz + row * NG + n0 + tc * 8);
        ulonglong2 v0; v0.x = acc[i][0]; v0.y = acc[i][1];
        ulonglong2 v1; v1.x = acc[i][2]; v1.y = acc[i][3];
        orow[0] = v0; orow[1] = v1;
    }
}

// ---------------------------------------------------------------------------
// Phase 2: LSTM recurrence, 2-CTA clusters, 256 threads/CTA.
// Thread (cg 0..63, kq 0..3): 4 gate-columns (2 hidden j's x both gate-pairs)
// over k-quarter kq (64 k's). Per k2: 4 coalesced LDG.128 (U), 10 broadcast
// LDS.128 (h dup pairs), 80 FFMA2. Step end: all write partials [4][256][10],
// sync, each thread finalizes its 2 j's for its seq subset, publishes h to
// both CTAs, cluster_sync.
// smem: h 2x256x10 u64 (40960) + part 4x64x4x10 u64 (81920)
//     + xz 2x10x512 f32 (40960) + mask 1280 = 165120 B.
// ---------------------------------------------------------------------------
#define XZS 512
#define LSTM_SMEM (2*256*LNS*8 + 4*64*4*LNS*8 + 2*LNS*XZS*4 + LNS*NT)

__global__ __launch_bounds__(256, 1) __cluster_dims__(2, 1, 1)
void lstm_kernel(float* __restrict__ out)
{
    extern __shared__ __align__(16) char dsm[];
    u64*   sh_h    = (u64*)dsm;                                   // [2][256][LNS]
    u64*   sh_part = (u64*)(dsm + 2*256*LNS*8);                   // [4][64][4][LNS]
    float* sh_xz   = (float*)(dsm + 2*256*LNS*8 + 4*64*4*LNS*8);  // [2][LNS][XZS]
    unsigned char* sh_m = (unsigned char*)(dsm + 2*256*LNS*8 + 4*64*4*LNS*8 + 2*LNS*XZS*4);

    const int tid  = threadIdx.x;
    const int cg   = tid & 63;
    const int kq   = tid >> 6;
    const int lane = cg & 31;
    const int half = cg >> 5;
    const int c    = blockIdx.x;          // == cluster rank
    const int grp  = blockIdx.y;
    const int d    = blockIdx.z;
    const int dc   = d * 2 + c;
    const int seq0 = grp * LNS;
    const int j0   = c * 128 + 2 * cg;    // this thread's first hidden index

    uint32_t rank; asm("mov.u32 %0, %%cluster_ctarank;" : "=r"(rank));
    const uint32_t my_h   = smem_u32(sh_h);
    const uint32_t peer_h = mapa_u32(my_h, rank ^ 1);
    const uint32_t xz_s32 = smem_u32(sh_xz);

    for (int i = tid; i < 256 * LNS; i += 256) sh_h[i] = 0ull;
    for (int i = tid; i < LNS * NT; i += 256)
        sh_m[i] = g_mask[(size_t)seq0 * NT + i];

    const float* xzb = g_xz + (size_t)d * NM * NG + (size_t)seq0 * NT * NG;

    // Prime xz stage for step 0 into buffer 0.
    {
        const int t0 = d ? (NT - 1) : 0;
        #pragma unroll
        for (int i = tid; i < 1280; i += 256){
            int s = i >> 7;
            int o = i & 127;
            int gcol = ((o >> 5) << 8) + c * 128 + ((o & 31) << 2);
            const float* src = xzb + ((size_t)s * NT + t0) * NG + gcol;
            uint32_t dst = xz_s32 + (uint32_t)((s * XZS + (o >> 5) * 128 + ((o & 31) << 2)) * 4);
            cp_async16(dst, src);
        }
        cp_async_commit();
        cp_async_wait0();
    }
    __syncthreads();

    // Sequence subset this thread finalizes.
    const int s0   = (kq < 2) ? kq * 3 : 6 + (kq - 2) * 2;
    const int scnt = (kq < 2) ? 3 : 2;
    float h_st[2][3], c_st[2][3];
    #pragma unroll
    for (int a = 0; a < 2; a++)
        #pragma unroll
        for (int b = 0; b < 3; b++){ h_st[a][b] = 0.f; c_st[a][b] = 0.f; }

    // U pointer: [dc][k2][half][q][lane][jlq]; this thread's k2 range starts at kq*32.
    const u64* Ubase = g_U6 + (((size_t)(dc * 128 + kq * 32) * 2 + half) * 4) * 64 + lane * 2;
    float* outb = out + (size_t)seq0 * NT * (2 * NH) + d * NH + j0;
    u64* pbase = sh_part + (((size_t)kq * 64 + cg) * 4) * LNS;

    int rb = 0;
    for (int step = 0; step < NT; ++step){
        const int t = d ? (NT - 1 - step) : step;

        // acc init: kq0 from staged xz, others zero. acc[colq][s], colq = gp*2+jlq.
        u64 acc[4][LNS];
        if (kq == 0){
            const float* xs = sh_xz + (size_t)rb * LNS * XZS;
            #pragma unroll
            for (int gp = 0; gp < 2; gp++)
                #pragma unroll
                for (int jlq = 0; jlq < 2; jlq++){
                    const int jl = 2 * cg + jlq;
                    #pragma unroll
                    for (int s = 0; s < LNS; s++)
                        acc[gp * 2 + jlq][s] =
                            pack2(xs[s * XZS + gp * 256 + jl], xs[s * XZS + gp * 256 + 128 + jl]);
                }
        } else {
            #pragma unroll
            for (int q = 0; q < 4; q++)
                #pragma unroll
                for (int s = 0; s < LNS; s++) acc[q][s] = 0ull;
        }

        // Kick xz prefetch for the next step into buffer rb^1.
        if (step < NT - 1){
            const int tn = d ? (NT - 2 - step) : (step + 1);
            #pragma unroll
            for (int i = tid; i < 1280; i += 256){
                int s = i >> 7;
                int o = i & 127;
                int gcol = ((o >> 5) << 8) + c * 128 + ((o & 31) << 2);
                const float* src = xzb + ((size_t)s * NT + tn) * NG + gcol;
                uint32_t dst = xz_s32 + (uint32_t)((((rb ^ 1) * LNS + s) * XZS
                                   + (o >> 5) * 128 + ((o & 31) << 2)) * 4);
                cp_async16(dst, src);
            }
        }
        cp_async_commit();

        // Main k-loop: 32 k2 (64 k's), distance-1 U prefetch.
        const u64* hbase = sh_h + (size_t)rb * 256 * LNS + (size_t)(kq * 64) * LNS;
        ulonglong2 Un[4];
        #pragma unroll
        for (int q = 0; q < 4; q++) Un[q] = *(const ulonglong2*)(Ubase + q * 64);
        #pragma unroll 2
        for (int i = 0; i < 32; i++){
            ulonglong2 Uq0 = Un[0], Uq1 = Un[1], Uq2 = Un[2], Uq3 = Un[3];
            if (i < 31){
                const u64* up = Ubase + (size_t)(i + 1) * 512;
                #pragma unroll
                for (int q = 0; q < 4; q++) Un[q] = *(const ulonglong2*)(up + q * 64);
            }
            const ulonglong2* hp = (const ulonglong2*)(hbase + i * 2 * LNS);
            ulonglong2 a0 = hp[0], a1 = hp[1], a2 = hp[2], a3 = hp[3], a4 = hp[4];
            ulonglong2 b0 = hp[5], b1 = hp[6], b2 = hp[7], b3 = hp[8], b4 = hp[9];
            u64 h0[LNS] = { a0.x, a0.y, a1.x, a1.y, a2.x, a2.y, a3.x, a3.y, a4.x, a4.y };
            u64 h1[LNS] = { b0.x, b0.y, b1.x, b1.y, b2.x, b2.y, b3.x, b3.y, b4.x, b4.y };
            #pragma unroll
            for (int s = 0; s < LNS; s++){
                acc[0][s] = ffma2(h0[s], Uq0.x, acc[0][s]);
                acc[1][s] = ffma2(h0[s], Uq0.y, acc[1][s]);
                acc[2][s] = ffma2(h0[s], Uq1.x, acc[2][s]);
                acc[3][s] = ffma2(h0[s], Uq1.y, acc[3][s]);
                acc[0][s] = ffma2(h1[s], Uq2.x, acc[0][s]);
                acc[1][s] = ffma2(h1[s], Uq2.y, acc[1][s]);
                acc[2][s] = ffma2(h1[s], Uq3.x, acc[2][s]);
                acc[3][s] = ffma2(h1[s], Uq3.y, acc[3][s]);
            }
        }

        // Write partials (all groups).
        #pragma unroll
        for (int q = 0; q < 4; q++){
            #pragma unroll
            for (int s = 0; s < LNS; s += 2){
                ulonglong2 v; v.x = acc[q][s]; v.y = acc[q][s + 1];
                *(ulonglong2*)&pbase[q * LNS + s] = v;
            }
        }
        __syncthreads();

        // Finalize: this thread's 2 hidden j's for seqs [s0, s0+scnt).
        {
            const int wb = rb ^ 1;
            const u64* pr = sh_part + ((size_t)cg * 4) * LNS;   // [kq][cg][colq][s] strided
            const size_t kqs = (size_t)64 * 4 * LNS;            // stride between kq slabs
            #pragma unroll
            for (int jlq = 0; jlq < 2; jlq++){
                #pragma unroll
                for (int si = 0; si < 3; si++){
                    if (si < scnt){
                        const int s = s0 + si;
                        u64 zif = addf32x2(addf32x2(pr[jlq * LNS + s], pr[kqs + jlq * LNS + s]),
                                           addf32x2(pr[2 * kqs + jlq * LNS + s], pr[3 * kqs + jlq * LNS + s]));
                        u64 zgo = addf32x2(addf32x2(pr[(2 + jlq) * LNS + s], pr[kqs + (2 + jlq) * LNS + s]),
                                           addf32x2(pr[2 * kqs + (2 + jlq) * LNS + s], pr[3 * kqs + (2 + jlq) * LNS + s]));
                        float zi, zf, zg, zo;
                        unpack2(zif, zi, zf);
                        unpack2(zgo, zg, zo);
                        float ig = 1.f / (1.f + __expf(-zi));
                        float fg = 1.f / (1.f + __expf(-zf));
                        float gg = 1.f - 2.f / (__expf(2.f * zg) + 1.f);
                        float og = 1.f / (1.f + __expf(-zo));
                        float cn = fg * c_st[jlq][si] + ig * gg;
                        float hn = og * (1.f - 2.f / (__expf(2.f * cn) + 1.f));
                        if (sh_m[s * NT + t]){ c_st[jlq][si] = cn; h_st[jlq][si] = hn; }
                        u64 hd = pack2(h_st[jlq][si], h_st[jlq][si]);
                        size_t hidx = (size_t)wb * 256 * LNS + (size_t)(j0 + jlq) * LNS + s;
                        sh_h[hidx] = hd;
                        st_cluster_u64(peer_h + (uint32_t)(hidx * 8), hd);
                        outb[((size_t)s * NT + t) * (2 * NH) + jlq] = h_st[jlq][si];
                    }
                }
            }
        }
        cp_async_wait0();
        cluster_sync();
        rb ^= 1;
    }
}

extern "C" void kernel_launch(void* const* d_in, const int* in_sizes, int n_in,
                              void* d_out, int out_size)
{
    const float*         facts = (const float*)d_in[0];
    const unsigned char* mask  = (const unsigned char*)d_in[1];
    const float*         Wf    = (const float*)d_in[2];
    const float*         Uf    = (const float*)d_in[3];
    const float*         bf    = (const float*)d_in[4];
    const float*         Wb    = (const float*)d_in[5];
    const float*         Ub    = (const float*)d_in[6];
    const float*         bb    = (const float*)d_in[7];
    float* out = (float*)d_out;

    cudaFuncSetAttribute(lstm_kernel, cudaFuncAttributeMaxDynamicSharedMemorySize, LSTM_SMEM);

    repack_u_kernel<<<1024, 256>>>(Uf, Ub);
    repack_mask_kernel<<<SEQS * NT / 256, 256>>>(mask);
    proj_kernel<<<dim3(NM / BM, 16), 256>>>(facts, Wf, bf, Wb, bb);
    lstm_kernel<<<dim3(2, SEQS / LNS, 2), 256, LSTM_SMEM>>>(out);
}

// round 7
// speedup vs baseline: 1.6510x; 1.0651x over previous
#include <cuda_runtime.h>
#include <cstdint>

typedef unsigned long long u64;

#define NB 16
#define NF 20
#define NT 128
#define ND 300
#define NH 256
#define NG 1024   // 4*H
#define SEQS 320  // NB*NF
#define NM 40960  // SEQS*NT
#define LNS 10    // sequences per lstm cluster (32 groups)

// Scratch: projection output (both dirs) 335 MB, repacked U 2 MB, mask 40 KB.
__device__ float g_xz[2ull * NM * NG];
// U layout: u64 idx = (((dc*128 + k2)*8 + q)*32 + cg5)*2 + kk
//   dc = d*2+c, k = 2*k2+kk, gp = q>>2, jl = cg5*4 + (q&3), j = c*128+jl
//   value = (U[k][gp*512 + j], U[k][gp*512 + 256 + j])
__device__ u64 g_U7[4 * 128 * 8 * 32 * 2];
__device__ unsigned char g_mask[SEQS * NT];

__device__ __forceinline__ u64 pack2(float a, float b){
    u64 r; asm("mov.b64 %0, {%1, %2};" : "=l"(r) : "f"(a), "f"(b)); return r;
}
__device__ __forceinline__ void unpack2(u64 v, float& a, float& b){
    asm("mov.b64 {%0, %1}, %2;" : "=f"(a), "=f"(b) : "l"(v));
}
__device__ __forceinline__ u64 ffma2(u64 a, u64 b, u64 c){
    u64 d; asm("fma.rn.f32x2 %0, %1, %2, %3;" : "=l"(d) : "l"(a), "l"(b), "l"(c)); return d;
}
__device__ __forceinline__ u64 addf32x2(u64 a, u64 b){
    u64 d; asm("add.rn.f32x2 %0, %1, %2;" : "=l"(d) : "l"(a), "l"(b)); return d;
}
__device__ __forceinline__ uint32_t smem_u32(const void* p){
    uint32_t a; asm("{ .reg .u64 t; cvta.to.shared.u64 t, %1; cvt.u32.u64 %0, t; }" : "=r"(a) : "l"(p));
    return a;
}
__device__ __forceinline__ uint32_t mapa_u32(uint32_t addr, uint32_t rank){
    uint32_t r; asm("mapa.shared::cluster.u32 %0, %1, %2;" : "=r"(r) : "r"(addr), "r"(rank));
    return r;
}
__device__ __forceinline__ void st_cluster_u64(uint32_t addr, u64 v){
    asm volatile("st.shared::cluster.u64 [%0], %1;" :: "r"(addr), "l"(v) : "memory");
}
__device__ __forceinline__ void cluster_sync(){
    asm volatile("barrier.cluster.arrive.aligned;\n\tbarrier.cluster.wait.aligned;" ::: "memory");
}
__device__ __forceinline__ void cp_async16(uint32_t sdst, const void* gsrc){
    asm volatile("cp.async.ca.shared.global [%0], [%1], 16;" :: "r"(sdst), "l"(gsrc) : "memory");
}
__device__ __forceinline__ void cp_async_commit(){
    asm volatile("cp.async.commit_group;" ::: "memory");
}
__device__ __forceinline__ void cp_async_wait0(){
    asm volatile("cp.async.wait_group 0;" ::: "memory");
}

// ---------------------------------------------------------------------------
// Repack U into the chunked, warp-coalesced layout described above.
// ---------------------------------------------------------------------------
__global__ void repack_u_kernel(const float* __restrict__ Uf, const float* __restrict__ Ub)
{
    int idx = blockIdx.x * 256 + threadIdx.x;   // 0 .. 262143 (u64 units)
    int kk  = idx & 1;
    int cg5 = (idx >> 1) & 31;
    int q   = (idx >> 6) & 7;
    int k2  = (idx >> 9) & 127;
    int dc  = (idx >> 16) & 3;
    int d = dc >> 1, c = dc & 1;
    int k  = 2 * k2 + kk;
    int gp = q >> 2;
    int jl = cg5 * 4 + (q & 3);
    int j  = c * 128 + jl;
    const float* U = d ? Ub : Uf;
    g_U7[idx] = pack2(U[(size_t)k * NG + gp * 512 + j],
                      U[(size_t)k * NG + gp * 512 + 256 + j]);
}

// ---------------------------------------------------------------------------
// Canonicalize mask to u8. mask[0][0], mask[0][1] guaranteed true (len >= 64):
// byte0==0 -> float32; byte1!=0 -> uint8; else -> int32.
// ---------------------------------------------------------------------------
__global__ void repack_mask_kernel(const unsigned char* __restrict__ raw)
{
    int idx = blockIdx.x * 256 + threadIdx.x;
    unsigned char b0 = raw[0], b1 = raw[1];
    unsigned char v;
    if (b0 == 0)      v = (((const float*)raw)[idx] != 0.0f);
    else if (b1 != 0) v = (raw[idx] != 0);
    else              v = (((const int*)raw)[idx] != 0);
    g_mask[idx] = v;
}

// ---------------------------------------------------------------------------
// Phase 1: xz = x @ W + b.  M=40960, K=300, N=1024 per dir. (unchanged)
// ---------------------------------------------------------------------------
#define BM 128
#define BN 128
#define BK 20
#define KT 300

__global__ __launch_bounds__(256, 2) void proj_kernel(
    const float* __restrict__ x,
    const float* __restrict__ Wf, const float* __restrict__ bf,
    const float* __restrict__ Wb, const float* __restrict__ bb)
{
    __shared__ u64  Asd[BK][BM + 2];
    __shared__ float Bs[BK][BN];

    const int tid = threadIdx.x;
    const int m0  = blockIdx.x * BM;
    const int d   = blockIdx.y >> 3;
    const int n0  = (blockIdx.y & 7) * BN;
    const float* __restrict__ W    = d ? Wb : Wf;
    const float* __restrict__ bias = d ? bb : bf;
    const int tc = tid & 15;
    const int tr = tid >> 4;

    u64 acc[8][4];
    {
        const float* bp = bias + n0 + tc * 8;
        u64 b0 = pack2(bp[0], bp[1]);
        u64 b1 = pack2(bp[2], bp[3]);
        u64 b2 = pack2(bp[4], bp[5]);
        u64 b3 = pack2(bp[6], bp[7]);
        #pragma unroll
        for (int i = 0; i < 8; i++){ acc[i][0]=b0; acc[i][1]=b1; acc[i][2]=b2; acc[i][3]=b3; }
    }

    for (int kt = 0; kt < KT; kt += BK){
        #pragma unroll
        for (int i = 0; i < 10; i++){
            int li = tid + i * 256;
            int m  = li / BK;
            int k  = li % BK;
            float v = x[(size_t)(m0 + m) * ND + kt + k];
            Asd[k][m] = pack2(v, v);
        }
        #pragma unroll
        for (int i = 0; i < 10; i++){
            int li = tid + i * 256;
            int k  = li >> 7;
            int n  = li & 127;
            Bs[k][n] = W[(size_t)(kt + k) * NG + n0 + n];
        }
        __syncthreads();

        #pragma unroll
        for (int k = 0; k < BK; k++){
            u64 a[8];
            {
                const ulonglong2* ap = (const ulonglong2*)&Asd[k][tr * 8];
                ulonglong2 a01 = ap[0], a23 = ap[1], a45 = ap[2], a67 = ap[3];
                a[0]=a01.x; a[1]=a01.y; a[2]=a23.x; a[3]=a23.y;
                a[4]=a45.x; a[5]=a45.y; a[6]=a67.x; a[7]=a67.y;
            }
            u64 b[4];
            {
                const ulonglong2* bp = (const ulonglong2*)&Bs[k][tc * 8];
                ulonglong2 b01 = bp[0], b23 = bp[1];
                b[0]=b01.x; b[1]=b01.y; b[2]=b23.x; b[3]=b23.y;
            }
            #pragma unroll
            for (int i = 0; i < 8; i++){
                #pragma unroll
                for (int j = 0; j < 4; j++){
                    acc[i][j] = ffma2(a[i], b[j], acc[i][j]);
                }
            }
        }
        __syncthreads();
    }

    #pragma unroll
    for (int i = 0; i < 8; i++){
        size_t row = (size_t)d * NM + (size_t)(m0 + tr * 8 + i);
        ulonglong2* orow = (ulonglong2*)(g_xz + row * NG + n0 + tc * 8);
        ulonglong2 v0; v0.x = acc[i][0]; v0.y = acc[i][1];
        ulonglong2 v1; v1.x = acc[i][2]; v1.y = acc[i][3];
        orow[0] = v0; orow[1] = v1;
    }
}

// ---------------------------------------------------------------------------
// Phase 2: LSTM recurrence, 2-CTA clusters, 256 threads/CTA.
// Thread (cg5, kq, sh): 8 pair-cols (jl = cg5*4+(q&3), gp = q>>2) over
// k-quarter kq (64 k's) for seq-half sh (5 seqs). Per k2-iter: 8 coalesced
// 16B U loads, 6 broadcast LDS.128 (h), 80 FFMA2; acc[8][5] = 80 regs.
// Step end: conflict-free partials [kq*2+sh][s][q][cg5]; finalize thread
// (jl2 = tid&63 -> j = 2*jl2+{0,1}; sq = tid>>6 -> 2-3 seqs) sums 4 kq
// partials + xz (cp.async-staged), applies gates, publishes h to both CTAs.
// smem: h 2*256*12 u64 (49152) + part 8*5*8*32 u64 (81920)
//     + xz 10*512 f32 (20480) + mask 1280 = 152832 B.
// ---------------------------------------------------------------------------
#define LSTM_SMEM (2*256*12*8 + 8*5*8*32*8 + LNS*512*4 + LNS*NT)

__global__ __launch_bounds__(256, 1) __cluster_dims__(2, 1, 1)
void lstm_kernel(float* __restrict__ out)
{
    extern __shared__ __align__(16) char dsm[];
    u64*   sh_h    = (u64*)dsm;                              // [2][256][12]
    u64*   sh_part = (u64*)(dsm + 2*256*12*8);               // [8][5][8][32]
    float* sh_xz   = (float*)(dsm + 2*256*12*8 + 8*5*8*32*8);// [10][512]
    unsigned char* sh_m = (unsigned char*)(dsm + 2*256*12*8 + 8*5*8*32*8 + LNS*512*4);

    const int tid  = threadIdx.x;
    const int cg5  = tid & 31;
    const int kq   = (tid >> 5) & 3;
    const int sh   = tid >> 7;
    const int c    = blockIdx.x;          // == cluster rank
    const int grp  = blockIdx.y;
    const int d    = blockIdx.z;
    const int dc   = d * 2 + c;
    const int seq0 = grp * LNS;

    uint32_t rank; asm("mov.u32 %0, %%cluster_ctarank;" : "=r"(rank));
    const uint32_t my_h   = smem_u32(sh_h);
    const uint32_t peer_h = mapa_u32(my_h, rank ^ 1);
    const uint32_t xz_s32 = smem_u32(sh_xz);

    for (int i = tid; i < 2 * 256 * 12; i += 256) sh_h[i] = 0ull;
    for (int i = tid; i < LNS * NT; i += 256)
        sh_m[i] = g_mask[(size_t)seq0 * NT + i];
    __syncthreads();

    const float* xzb = g_xz + (size_t)d * NM * NG + (size_t)seq0 * NT * NG;

    // Finalize assignment: thread owns j = 2*jl2 + {0,1}, seqs [fs0, fs0+fscnt).
    const int jl2   = tid & 63;
    const int sq    = tid >> 6;
    const int fs0   = (sq == 0) ? 0 : (sq == 1) ? 3 : (sq == 2) ? 5 : 8;
    const int fscnt = (sq & 1) ? 2 : 3;
    float h_st[2][3], c_st[2][3];
    #pragma unroll
    for (int a = 0; a < 2; a++)
        #pragma unroll
        for (int b = 0; b < 3; b++){ h_st[a][b] = 0.f; c_st[a][b] = 0.f; }

    // k-loop pointers.
    const ulonglong2* Ubase = (const ulonglong2*)g_U7
                            + ((size_t)(dc * 128 + kq * 32) * 8) * 32 + cg5;
    u64* pbase = sh_part + ((size_t)(kq * 2 + sh) * 5) * 256;   // + s*256 + q*32 + cg5

    int rb = 0;
    for (int step = 0; step < NT; ++step){
        const int t = d ? (NT - 1 - step) : step;

        // Stage xz[t] for this CTA's 512 gate-cols x 10 seqs (read at finalize).
        #pragma unroll
        for (int i = tid; i < 1280; i += 256){
            int s = i >> 7;
            int o = i & 127;
            int gcol = ((o >> 5) << 8) + c * 128 + ((o & 31) << 2);
            const float* src = xzb + ((size_t)s * NT + t) * NG + gcol;
            uint32_t dst = xz_s32 + (uint32_t)((s * 512 + (o >> 5) * 128 + ((o & 31) << 2)) * 4);
            cp_async16(dst, src);
        }
        cp_async_commit();

        // Main k-loop: 32 k2-iters (64 k's).
        u64 acc[8][5];
        #pragma unroll
        for (int q = 0; q < 8; q++)
            #pragma unroll
            for (int s = 0; s < 5; s++) acc[q][s] = 0ull;

        const u64* hb = sh_h + (size_t)rb * 256 * 12 + (size_t)(kq * 64) * 12 + sh * 6;
        #pragma unroll 4
        for (int i = 0; i < 32; i++){
            ulonglong2 Uq[8];
            #pragma unroll
            for (int q = 0; q < 8; q++) Uq[q] = Ubase[((size_t)i * 8 + q) * 32];
            const ulonglong2* h0p = (const ulonglong2*)(hb + (2 * i) * 12);
            const ulonglong2* h1p = (const ulonglong2*)(hb + (2 * i + 1) * 12);
            ulonglong2 a0 = h0p[0], a1 = h0p[1], a2 = h0p[2];
            ulonglong2 b0 = h1p[0], b1 = h1p[1], b2 = h1p[2];
            u64 h0[5] = { a0.x, a0.y, a1.x, a1.y, a2.x };
            u64 h1[5] = { b0.x, b0.y, b1.x, b1.y, b2.x };
            #pragma unroll
            for (int q = 0; q < 8; q++){
                #pragma unroll
                for (int s = 0; s < 5; s++){
                    acc[q][s] = ffma2(h0[s], Uq[q].x, acc[q][s]);
                    acc[q][s] = ffma2(h1[s], Uq[q].y, acc[q][s]);
                }
            }
        }

        // Conflict-free partial writes: [kq*2+sh][s][q][cg5].
        #pragma unroll
        for (int s = 0; s < 5; s++)
            #pragma unroll
            for (int q = 0; q < 8; q++)
                pbase[s * 256 + q * 32 + cg5] = acc[q][s];

        cp_async_wait0();
        __syncthreads();

        // Finalize.
        {
            const int wb = rb ^ 1;
            #pragma unroll
            for (int w = 0; w < 2; w++){
                const int jl  = 2 * jl2 + w;
                const int j   = c * 128 + jl;
                const int qm  = jl & 3;
                const int cgx = jl >> 2;
                float* outc = out + ((size_t)(seq0) * NT + t) * (2 * NH) + d * NH + j;
                #pragma unroll
                for (int si = 0; si < 3; si++){
                    if (si < fscnt){
                        const int s   = fs0 + si;
                        const int shs = (s >= 5);
                        const int sl  = s - 5 * shs;
                        // Sum 4 kq partials for (gp0, gp1) + xz.
                        const u64* pif = sh_part + ((size_t)sl * 256 + qm * 32 + cgx) + (size_t)shs * 5 * 256;
                        const u64* pgo = pif + 128;   // q = 4+qm -> +4*32
                        u64 zif = addf32x2(addf32x2(pif[0], pif[2560]),
                                           addf32x2(pif[5120], pif[7680]));
                        u64 zgo = addf32x2(addf32x2(pgo[0], pgo[2560]),
                                           addf32x2(pgo[5120], pgo[7680]));
                        const float* xs = sh_xz + s * 512;
                        zif = addf32x2(zif, pack2(xs[jl], xs[128 + jl]));
                        zgo = addf32x2(zgo, pack2(xs[256 + jl], xs[384 + jl]));
                        float zi, zf, zg, zo;
                        unpack2(zif, zi, zf);
                        unpack2(zgo, zg, zo);
                        float ig = 1.f / (1.f + __expf(-zi));
                        float fg = 1.f / (1.f + __expf(-zf));
                        float gg = 1.f - 2.f / (__expf(2.f * zg) + 1.f);
                        float og = 1.f / (1.f + __expf(-zo));
                        float cn = fg * c_st[w][si] + ig * gg;
                        float hn = og * (1.f - 2.f / (__expf(2.f * cn) + 1.f));
                        if (sh_m[s * NT + t]){ c_st[w][si] = cn; h_st[w][si] = hn; }
                        u64 hd = pack2(h_st[w][si], h_st[w][si]);
                        size_t hidx = ((size_t)wb * 256 + j) * 12 + shs * 6 + sl;
                        sh_h[hidx] = hd;
                        st_cluster_u64(peer_h + (uint32_t)(hidx * 8), hd);
                        outc[(size_t)s * NT * (2 * NH)] = h_st[w][si];
                    }
                }
            }
        }
        cluster_sync();
        rb ^= 1;
    }
}

extern "C" void kernel_launch(void* const* d_in, const int* in_sizes, int n_in,
                              void* d_out, int out_size)
{
    const float*         facts = (const float*)d_in[0];
    const unsigned char* mask  = (const unsigned char*)d_in[1];
    const float*         Wf    = (const float*)d_in[2];
    const float*         Uf    = (const float*)d_in[3];
    const float*         bf    = (const float*)d_in[4];
    const float*         Wb    = (const float*)d_in[5];
    const float*         Ub    = (const float*)d_in[6];
    const float*         bb    = (const float*)d_in[7];
    float* out = (float*)d_out;

    cudaFuncSetAttribute(lstm_kernel, cudaFuncAttributeMaxDynamicSharedMemorySize, LSTM_SMEM);

    repack_u_kernel<<<1024, 256>>>(Uf, Ub);
    repack_mask_kernel<<<SEQS * NT / 256, 256>>>(mask);
    proj_kernel<<<dim3(NM / BM, 16), 256>>>(facts, Wf, bf, Wb, bb);
    lstm_kernel<<<dim3(2, SEQS / LNS, 2), 256, LSTM_SMEM>>>(out);
}